// round 5
// baseline (speedup 1.0000x reference)
#include <cuda_runtime.h>

#define N_NODES 8192
#define DIN 128
#define DOUT 128
#define E_EDGES 262144
#define MWORDS 256          // 8192 bits / 32 per adjacency row
#define MAXD 128            // max unique out-degree (Poisson(32): P(>96) ~ 1e-11)

// ---- scratch (device globals; no allocation allowed) ----
__device__ int      g_deg[N_NODES];
__device__ int      g_cnt[N_NODES];
__device__ unsigned g_mask[N_NODES * MWORDS];      // 8 MB dedup bitmask
__device__ int      g_nbr[N_NODES * MAXD];         // byte offsets (c*512) of unique nbrs
__device__ float    g_feat[N_NODES * DOUT];        // 4 MB: g[j] = dinv[j]*(x[j]W^T + b)
__device__ float    g_wt[DIN * DOUT];              // W^T: g_wt[k*128+c] = W[c][k]

// packed f32x2 FMA: d = a*b + d elementwise on {lo,hi} fp32 pairs (FFMA2 SASS)
__device__ __forceinline__ void ffma2(unsigned long long& acc,
                                      unsigned long long a, unsigned long long b) {
    asm("fma.rn.f32x2 %0, %1, %2, %0;" : "+l"(acc) : "l"(a), "l"(b));
}
__device__ __forceinline__ unsigned long long dup2(float v) {
    unsigned long long r;
    asm("mov.b64 %0, {%1, %1};" : "=l"(r) : "f"(v));
    return r;
}
__device__ __forceinline__ float2 unpack2(unsigned long long v) {
    float2 f;
    asm("mov.b64 {%0, %1}, %2;" : "=f"(f.x), "=f"(f.y) : "l"(v));
    return f;
}

// ------------------------------------------------------- zero scratch + W^T
__global__ void k_prep(const float* __restrict__ W) {
    int idx = blockIdx.x * blockDim.x + threadIdx.x;
    int stride = gridDim.x * blockDim.x;
    uint4 z = make_uint4(0, 0, 0, 0);
    const int nm4 = (N_NODES * MWORDS) / 4;
    for (int i = idx; i < nm4; i += stride) ((uint4*)g_mask)[i] = z;
    if (idx < N_NODES) { g_deg[idx] = 0; g_cnt[idx] = 0; }
    if (idx < DIN * DOUT) {                       // transpose W (coalesced write)
        int k = idx / DOUT, c = idx % DOUT;
        g_wt[k * DOUT + c] = W[c * DIN + k];
    }
}

// ---------------------------------------------------------------- edge pass
// deg counts ALL edges (multiplicity, matches .at[row].add); bitmask dedups
// adjacency (matches .at[row,col].set). First setter appends the neighbor's
// BYTE OFFSET into g_feat (c*512) so the gather needs only one IADD per load.
__global__ void k_edges(const int* __restrict__ ei) {
    int e = blockIdx.x * blockDim.x + threadIdx.x;
    if (e >= E_EDGES) return;
    int r = ei[e];
    int c = ei[E_EDGES + e];
    atomicAdd(&g_deg[r], 1);                       // no return use -> REDG
    unsigned m = 1u << (c & 31);
    unsigned old = atomicOr(&g_mask[r * MWORDS + (c >> 5)], m);
    if (!(old & m)) {
        int p = atomicAdd(&g_cnt[r], 1);
        if (p < MAXD) g_nbr[r * MAXD + p] = c << 9;   // c * 512 bytes
    }
}

__device__ __forceinline__ float dinv_of(int d) {
    return (d > 0) ? rsqrtf((float)d) : 0.0f;
}

// ---------------------------------------------------------------- fused GEMM
// g_feat[i] = dinv[i] * (x[i] @ W^T + b). 64 rows/block, 256 threads.
// warp w owns rows w*8..w*8+7; lane l owns cols 4l..4l+3 as two f32x2 pairs.
#define GROWS 64
__global__ __launch_bounds__(256) void k_gemm(const float* __restrict__ x,
                                              const float* __restrict__ bias) {
    __shared__ float xs[GROWS][DIN];   // 32 KB
    const int row0 = blockIdx.x * GROWS;
    const int t = threadIdx.x;

    // load x tile: 8192 floats = 256 threads * 8 float4, fully coalesced
    const float4* xin = (const float4*)(x + row0 * DIN);
    float4* xs4 = (float4*)&xs[0][0];
#pragma unroll
    for (int i = 0; i < 8; i++) xs4[t + 256 * i] = xin[t + 256 * i];
    __syncthreads();

    const int w = t >> 5, l = t & 31;
    const int r0 = w * 8;
    const int c0 = l * 4;

    unsigned long long acc[8][2];
#pragma unroll
    for (int r = 0; r < 8; r++) { acc[r][0] = 0ull; acc[r][1] = 0ull; }

#pragma unroll 2
    for (int k = 0; k < DIN; k += 4) {
        ulonglong2 wv[4];                           // w[k+j][c0..c0+3] as 2 pairs
#pragma unroll
        for (int j = 0; j < 4; j++)
            wv[j] = *(const ulonglong2*)&g_wt[(k + j) * DOUT + c0];
#pragma unroll
        for (int r = 0; r < 8; r++) {
            float4 xv = *(const float4*)&xs[r0 + r][k];   // broadcast LDS.128
            unsigned long long x2;
            x2 = dup2(xv.x); ffma2(acc[r][0], x2, wv[0].x); ffma2(acc[r][1], x2, wv[0].y);
            x2 = dup2(xv.y); ffma2(acc[r][0], x2, wv[1].x); ffma2(acc[r][1], x2, wv[1].y);
            x2 = dup2(xv.z); ffma2(acc[r][0], x2, wv[2].x); ffma2(acc[r][1], x2, wv[2].y);
            x2 = dup2(xv.w); ffma2(acc[r][0], x2, wv[3].x); ffma2(acc[r][1], x2, wv[3].y);
        }
    }

    float4 bv = *(const float4*)&bias[c0];
#pragma unroll
    for (int r = 0; r < 8; r++) {
        int row = row0 + r0 + r;
        float dv = dinv_of(g_deg[row]);
        float2 lo = unpack2(acc[r][0]);
        float2 hi = unpack2(acc[r][1]);
        float4 o;
        o.x = dv * (lo.x + bv.x);
        o.y = dv * (lo.y + bv.y);
        o.z = dv * (hi.x + bv.z);
        o.w = dv * (hi.y + bv.w);
        *(float4*)&g_feat[row * DOUT + c0] = o;
    }
}

// ---------------------------------------------------------------- aggregation
// Warp per node: lane l owns features 4l..4l+3 (one LDG.128 per neighbor).
// 8 independent loads in flight per lane to hide L2 latency (~240 cyc).
// out[i][:] = relu( dinv[i] * sum_{j in uniq-nbrs(i)} g_feat[j][:] )
__global__ __launch_bounds__(256) void k_agg(float* __restrict__ out) {
    __shared__ int nb[8][MAXD];                    // byte offsets, 4 KB
    const int w = threadIdx.x >> 5, l = threadIdx.x & 31;
    const int i = blockIdx.x * 8 + w;
    int cnt = g_cnt[i];
    if (cnt > MAXD) cnt = MAXD;
    for (int p = l; p < cnt; p += 32) nb[w][p] = g_nbr[i * MAXD + p];
    __syncwarp();

    const char* base = (const char*)g_feat + l * 16;
    float4 a[8];
#pragma unroll
    for (int u = 0; u < 8; u++) a[u] = make_float4(0.f, 0.f, 0.f, 0.f);

    int p = 0;
    for (; p + 8 <= cnt; p += 8) {                 // 8 LDG.128 in flight per lane
        float4 v[8];
#pragma unroll
        for (int u = 0; u < 8; u++) v[u] = *(const float4*)(base + nb[w][p + u]);
#pragma unroll
        for (int u = 0; u < 8; u++) {
            a[u].x += v[u].x; a[u].y += v[u].y; a[u].z += v[u].z; a[u].w += v[u].w;
        }
    }
    for (; p < cnt; p++) {
        float4 v = *(const float4*)(base + nb[w][p]);
        a[0].x += v.x; a[0].y += v.y; a[0].z += v.z; a[0].w += v.w;
    }

#pragma unroll
    for (int u = 4; u < 8; u++) {                  // tree-reduce 8 -> 4 -> 1
        a[u - 4].x += a[u].x; a[u - 4].y += a[u].y;
        a[u - 4].z += a[u].z; a[u - 4].w += a[u].w;
    }
    float dv = dinv_of(g_deg[i]);
    float4 o;
    o.x = dv * ((a[0].x + a[1].x) + (a[2].x + a[3].x));
    o.y = dv * ((a[0].y + a[1].y) + (a[2].y + a[3].y));
    o.z = dv * ((a[0].z + a[1].z) + (a[2].z + a[3].z));
    o.w = dv * ((a[0].w + a[1].w) + (a[2].w + a[3].w));
    o.x = o.x > 0.f ? o.x : 0.f;
    o.y = o.y > 0.f ? o.y : 0.f;
    o.z = o.z > 0.f ? o.z : 0.f;
    o.w = o.w > 0.f ? o.w : 0.f;
    *(float4*)&out[i * DOUT + l * 4] = o;
}

// ---------------------------------------------------------------- launch
extern "C" void kernel_launch(void* const* d_in, const int* in_sizes, int n_in,
                              void* d_out, int out_size) {
    const float* x    = (const float*)d_in[0];   // [8192,128] f32
    const int*   ei   = (const int*)d_in[1];     // [2,262144] i32
    const float* W    = (const float*)d_in[2];   // [128,128]  f32
    const float* bias = (const float*)d_in[3];   // [128]      f32
    float* out = (float*)d_out;                  // [8192,128] f32

    k_prep <<<512, 256>>>(W);
    k_edges<<<E_EDGES / 256, 256>>>(ei);
    k_gemm <<<N_NODES / GROWS, 256>>>(x, bias);
    k_agg  <<<N_NODES / 8, 256>>>(out);
}

// round 6
// speedup vs baseline: 1.3467x; 1.3467x over previous
#include <cuda_runtime.h>
#include <cuda_fp16.h>

#define N_NODES 8192
#define DIN 128
#define DOUT 128
#define E_EDGES 262144
#define MWORDS 256          // 8192 bits / 32 per adjacency row
#define MAXD 128            // max unique out-degree (Poisson(32): P(>96) ~ 1e-11)
#define ROWB 256            // bytes per g_feat_h row (128 fp16)
#define ZERO_OFF (N_NODES * ROWB)   // byte offset of the permanent zero row

// ---- scratch (device globals; zero-initialized at module load).
// INVARIANT: g_mask / g_cnt / g_deg are all-zero at entry AND exit of every
// kernel_launch call (k_agg restores them), so no per-call memset is needed.
__device__ int      g_deg[N_NODES];
__device__ int      g_cnt[N_NODES];
__device__ unsigned g_mask[N_NODES * MWORDS];      // dedup bitmask (8 MB, sparse-touched)
__device__ int      g_nbr[N_NODES * MAXD];         // byte offsets (c*256) of unique nbrs
__device__ __half   g_feat_h[(N_NODES + 1) * DOUT];// fp16 g[j]=dinv[j]*(x W^T+b); row N = 0
__device__ float    g_wt[DIN * DOUT];              // W^T: g_wt[k*128+c] = W[c][k]

// packed f32x2 FMA helpers (FFMA2 SASS — ptxas never auto-fuses from C++)
__device__ __forceinline__ void ffma2(unsigned long long& acc,
                                      unsigned long long a, unsigned long long b) {
    asm("fma.rn.f32x2 %0, %1, %2, %0;" : "+l"(acc) : "l"(a), "l"(b));
}
__device__ __forceinline__ unsigned long long dup2(float v) {
    unsigned long long r;
    asm("mov.b64 %0, {%1, %1};" : "=l"(r) : "f"(v));
    return r;
}
__device__ __forceinline__ float2 unpack2(unsigned long long v) {
    float2 f;
    asm("mov.b64 {%0, %1}, %2;" : "=f"(f.x), "=f"(f.y) : "l"(v));
    return f;
}

__device__ __forceinline__ float dinv_of(int d) {
    return (d > 0) ? rsqrtf((float)d) : 0.0f;
}

// ------------------------------------------------------------ W^T only
__global__ void k_prep(const float* __restrict__ W) {
    int idx = blockIdx.x * blockDim.x + threadIdx.x;   // 16384 threads
    int k = idx / DOUT, c = idx % DOUT;                // coalesced writes
    g_wt[k * DOUT + c] = W[c * DIN + k];
}

// ---------------------------------------------------------------- edge pass
// deg counts ALL edges (multiplicity, matches .at[row].add); bitmask dedups
// adjacency (matches .at[row,col].set). First setter appends the neighbor's
// BYTE OFFSET into g_feat_h (c*256).
__global__ void k_edges(const int* __restrict__ ei) {
    int e = blockIdx.x * blockDim.x + threadIdx.x;
    if (e >= E_EDGES) return;
    int r = ei[e];
    int c = ei[E_EDGES + e];
    atomicAdd(&g_deg[r], 1);                       // no return use -> REDG
    unsigned m = 1u << (c & 31);
    unsigned old = atomicOr(&g_mask[r * MWORDS + (c >> 5)], m);
    if (!(old & m)) {
        int p = atomicAdd(&g_cnt[r], 1);
        if (p < MAXD) g_nbr[r * MAXD + p] = c << 8;   // c * 256 bytes
    }
}

// ---------------------------------------------------------------- fused GEMM
// g_feat_h[i] = fp16( dinv[i] * (x[i] @ W^T + b) ). 64 rows/block, 256 thr.
// warp w owns rows w*8..w*8+7; lane l owns cols 4l..4l+3 as two f32x2 pairs.
#define GROWS 64
__global__ __launch_bounds__(256) void k_gemm(const float* __restrict__ x,
                                              const float* __restrict__ bias) {
    __shared__ float xs[GROWS][DIN];   // 32 KB
    const int row0 = blockIdx.x * GROWS;
    const int t = threadIdx.x;

    const float4* xin = (const float4*)(x + row0 * DIN);
    float4* xs4 = (float4*)&xs[0][0];
#pragma unroll
    for (int i = 0; i < 8; i++) xs4[t + 256 * i] = xin[t + 256 * i];
    __syncthreads();

    const int w = t >> 5, l = t & 31;
    const int r0 = w * 8;
    const int c0 = l * 4;

    unsigned long long acc[8][2];
#pragma unroll
    for (int r = 0; r < 8; r++) { acc[r][0] = 0ull; acc[r][1] = 0ull; }

#pragma unroll 2
    for (int k = 0; k < DIN; k += 4) {
        ulonglong2 wv[4];
#pragma unroll
        for (int j = 0; j < 4; j++)
            wv[j] = *(const ulonglong2*)&g_wt[(k + j) * DOUT + c0];
#pragma unroll
        for (int r = 0; r < 8; r++) {
            float4 xv = *(const float4*)&xs[r0 + r][k];   // broadcast LDS.128
            unsigned long long x2;
            x2 = dup2(xv.x); ffma2(acc[r][0], x2, wv[0].x); ffma2(acc[r][1], x2, wv[0].y);
            x2 = dup2(xv.y); ffma2(acc[r][0], x2, wv[1].x); ffma2(acc[r][1], x2, wv[1].y);
            x2 = dup2(xv.z); ffma2(acc[r][0], x2, wv[2].x); ffma2(acc[r][1], x2, wv[2].y);
            x2 = dup2(xv.w); ffma2(acc[r][0], x2, wv[3].x); ffma2(acc[r][1], x2, wv[3].y);
        }
    }

    float4 bv = *(const float4*)&bias[c0];
#pragma unroll
    for (int r = 0; r < 8; r++) {
        int row = row0 + r0 + r;
        float dv = dinv_of(g_deg[row]);
        float2 lo = unpack2(acc[r][0]);
        float2 hi = unpack2(acc[r][1]);
        __half2 h01 = __floats2half2_rn(dv * (lo.x + bv.x), dv * (lo.y + bv.y));
        __half2 h23 = __floats2half2_rn(dv * (hi.x + bv.z), dv * (hi.y + bv.w));
        uint2 pk;
        pk.x = *reinterpret_cast<unsigned*>(&h01);
        pk.y = *reinterpret_cast<unsigned*>(&h23);
        *reinterpret_cast<uint2*>((char*)g_feat_h + row * ROWB + c0 * 2) = pk;
    }
}

// ---------------------------------------------------------------- aggregation
// Warp per node. Half-warp per neighbor: lane l reads the 16 bytes
// (features (l&15)*8 .. +7, 8 fp16) of neighbor nb[p + (l>>4)] in one LDG.128.
// 4 LDG.128 in flight per lane (8 neighbors per warp iteration). fp32 accum;
// cross-half-warp fold via shfl_xor(16). Also RESTORES the scratch invariant.
__global__ __launch_bounds__(256) void k_agg(float* __restrict__ out) {
    __shared__ int nb[8][MAXD];
    const int w = threadIdx.x >> 5, l = threadIdx.x & 31;
    const int i = blockIdx.x * 8 + w;
    const int half = l >> 4;
    const int fl = l & 15;

    int cnt = g_cnt[i];
    if (cnt > MAXD) cnt = MAXD;
    int deg = g_deg[i];

    for (int p = l; p < cnt; p += 32) nb[w][p] = g_nbr[i * MAXD + p];
    int cnt_pad = (cnt + 7) & ~7;
    for (int p = cnt + l; p < cnt_pad; p += 32) nb[w][p] = ZERO_OFF;  // pad -> zero row
    __syncwarp();

    const char* base = (const char*)g_feat_h + fl * 16;
    float2 a0[4], a1[4];
#pragma unroll
    for (int j = 0; j < 4; j++) {
        a0[j] = make_float2(0.f, 0.f);
        a1[j] = make_float2(0.f, 0.f);
    }

    for (int p = 0; p < cnt_pad; p += 8) {
        uint4 v[4];
#pragma unroll
        for (int u = 0; u < 4; u++)
            v[u] = *(const uint4*)(base + nb[w][p + 2 * u + half]);
#pragma unroll
        for (int u = 0; u < 4; u++) {
            const __half2* h = reinterpret_cast<const __half2*>(&v[u]);
            float2* a = (u & 1) ? a1 : a0;
#pragma unroll
            for (int j = 0; j < 4; j++) {
                float2 f = __half22float2(h[j]);
                a[j].x += f.x;
                a[j].y += f.y;
            }
        }
    }

    float r[8];
#pragma unroll
    for (int j = 0; j < 4; j++) {
        r[2 * j]     = a0[j].x + a1[j].x;
        r[2 * j + 1] = a0[j].y + a1[j].y;
    }
#pragma unroll
    for (int k = 0; k < 8; k++)                      // fold the two half-warps
        r[k] += __shfl_xor_sync(0xffffffffu, r[k], 16);

    float dv = dinv_of(deg);
    if (l < 16) {
        float4 o0, o1;
        o0.x = dv * r[0]; o0.y = dv * r[1]; o0.z = dv * r[2]; o0.w = dv * r[3];
        o1.x = dv * r[4]; o1.y = dv * r[5]; o1.z = dv * r[6]; o1.w = dv * r[7];
        o0.x = o0.x > 0.f ? o0.x : 0.f;  o0.y = o0.y > 0.f ? o0.y : 0.f;
        o0.z = o0.z > 0.f ? o0.z : 0.f;  o0.w = o0.w > 0.f ? o0.w : 0.f;
        o1.x = o1.x > 0.f ? o1.x : 0.f;  o1.y = o1.y > 0.f ? o1.y : 0.f;
        o1.z = o1.z > 0.f ? o1.z : 0.f;  o1.w = o1.w > 0.f ? o1.w : 0.f;
        float4* dst = (float4*)&out[i * DOUT + fl * 8];
        dst[0] = o0;
        dst[1] = o1;
    }

    // ---- restore scratch invariant (only touched words, no 8 MB memset) ----
    for (int p = l; p < cnt; p += 32)
        g_mask[i * MWORDS + (nb[w][p] >> 13)] = 0;   // (c*256)>>8>>5
    if (l == 0) { g_cnt[i] = 0; g_deg[i] = 0; }
}

// ---------------------------------------------------------------- launch
extern "C" void kernel_launch(void* const* d_in, const int* in_sizes, int n_in,
                              void* d_out, int out_size) {
    const float* x    = (const float*)d_in[0];   // [8192,128] f32
    const int*   ei   = (const int*)d_in[1];     // [2,262144] i32
    const float* W    = (const float*)d_in[2];   // [128,128]  f32
    const float* bias = (const float*)d_in[3];   // [128]      f32
    float* out = (float*)d_out;                  // [8192,128] f32

    k_prep <<<64, 256>>>(W);
    k_edges<<<E_EDGES / 256, 256>>>(ei);
    k_gemm <<<N_NODES / GROWS, 256>>>(x, bias);
    k_agg  <<<N_NODES / 8, 256>>>(out);
}